// round 4
// baseline (speedup 1.0000x reference)
#include <cuda_runtime.h>
#include <float.h>

// TropicalLinear: out[n,o] = bias[o] + max_k( x[n,k] + w[o,k] )
// N=128, IN=1024, OUT=1024, fp32.  (soft - stop_grad(soft) == 0 exactly)
//
// Single fused kernel, 144 CTAs (one wave, all co-resident):
//   part A: split-K max-plus GEMM (scalar FADD+FMNMX, no packing) -> g_part
//   grid barrier (arrive counter, spin; safe reset via depart counter)
//   part B: 18-way split reduction + bias -> out  (L2-hot scratch)

#define N_ROWS  128
#define IN_DIM  1024
#define OUT_DIM 1024

#define KSPLIT  18                 // 4 chunks of 60 + 14 chunks of 56 = 1024
#define KCMAX   60
#define TO      128
#define THREADS 512
#define NCTAS   (8 * KSPLIT)       // 144

#define XS_BYTES (KCMAX * N_ROWS * 4)    // 30720
#define WS_BYTES (KCMAX * TO * 4)        // 30720
#define SMEM_BYTES (XS_BYTES + WS_BYTES) // 61440

// 18 * 128 * 1024 * 4B = 9.4 MB scratch (stays L2-resident)
__device__ float g_part[KSPLIT * N_ROWS * OUT_DIM];
__device__ unsigned g_arrive;   // zero-init; restored to 0 each run
__device__ unsigned g_depart;   // zero-init; restored to 0 each run

__global__ __launch_bounds__(THREADS, 1)
void tropical_fused(const float* __restrict__ x, const float* __restrict__ w,
                    const float* __restrict__ bias, float* __restrict__ out)
{
    extern __shared__ char smem[];
    float* xs = (float*)smem;                    // [kc][128]
    float* ws = (float*)(smem + XS_BYTES);       // [kc][128]

    const int bo = blockIdx.x;                   // 0..7
    const int ks = blockIdx.y;                   // 0..17
    const int t  = threadIdx.x;

    const int kc = (ks < 4) ? 60 : 56;
    const int k0 = 56 * ks + 4 * min(ks, 4);
    const int o0 = bo * TO;

    // ---- fill transposed tiles; STS lanes vary along row dim -> bank-clean ----
    {
        const int r   = t & 127;
        const int kq  = t >> 7;                  // 0..3
        const int nf4 = kc >> 2;                 // 14 or 15

        const float4* xsrc = (const float4*)(x + (size_t)r * IN_DIM + k0);
        for (int f = kq; f < nf4; f += 4) {
            float4 v = __ldg(xsrc + f);
            int k = 4 * f;
            xs[(k + 0) * 128 + r] = v.x;
            xs[(k + 1) * 128 + r] = v.y;
            xs[(k + 2) * 128 + r] = v.z;
            xs[(k + 3) * 128 + r] = v.w;
        }
        const float4* wsrc = (const float4*)(w + (size_t)(o0 + r) * IN_DIM + k0);
        for (int f = kq; f < nf4; f += 4) {
            float4 v = __ldg(wsrc + f);
            int k = 4 * f;
            ws[(k + 0) * 128 + r] = v.x;
            ws[(k + 1) * 128 + r] = v.y;
            ws[(k + 2) * 128 + r] = v.z;
            ws[(k + 3) * 128 + r] = v.w;
        }
    }
    __syncthreads();

    // ---- GEMM body: 8 n x 4 o per thread ----
    //   og = lane (0..31): o = 4*og      -> warp covers o 0..127, conflict-free LDS.128
    //   ng = warp  (0..15): n = 8*ng+i   -> broadcast LDS.128 x2
    const int og = t & 31;
    const int ng = t >> 5;

    float acc[8][4];
    #pragma unroll
    for (int i = 0; i < 8; i++)
        #pragma unroll
        for (int j = 0; j < 4; j++)
            acc[i][j] = -FLT_MAX;

    const float4* xs4 = (const float4*)xs;       // [kc][32]
    const float4* ws4 = (const float4*)ws;       // [kc][32]

    #pragma unroll 4
    for (int k = 0; k < kc; k++) {
        float4 xa = xs4[k * 32 + ng * 2];
        float4 xb = xs4[k * 32 + ng * 2 + 1];
        float4 wv = ws4[k * 32 + og];
        float ax[8] = {xa.x, xa.y, xa.z, xa.w, xb.x, xb.y, xb.z, xb.w};
        float aw[4] = {wv.x, wv.y, wv.z, wv.w};
        #pragma unroll
        for (int i = 0; i < 8; i++) {
            #pragma unroll
            for (int j = 0; j < 4; j++) {
                acc[i][j] = fmaxf(acc[i][j], ax[i] + aw[j]);
            }
        }
    }

    // ---- write partials: g_part[ks][n][o], coalesced float4 stores ----
    {
        float4* dst = (float4*)g_part
            + ((size_t)ks * N_ROWS + ng * 8) * (OUT_DIM / 4) + bo * 32 + og;
        #pragma unroll
        for (int i = 0; i < 8; i++) {
            dst[(size_t)i * (OUT_DIM / 4)] =
                make_float4(acc[i][0], acc[i][1], acc[i][2], acc[i][3]);
        }
    }

    // ---- grid barrier: all 144 CTAs co-resident -> spin is safe ----
    __syncthreads();
    __threadfence();
    if (t == 0) {
        atomicAdd(&g_arrive, 1u);
        while (*(volatile unsigned*)&g_arrive < NCTAS) { }
    }
    __syncthreads();
    __threadfence();

    // ---- reduction tail: 2 threads per float4 output, 9 splits each ----
    {
        const int bid = ks * 8 + bo;
        const int gid = bid * THREADS + t;               // 0..73727
        if (gid < 2 * (N_ROWS * OUT_DIM / 4)) {          // 65536 active
            const int idx  = gid >> 1;                   // float4 out index
            const int half = gid & 1;

            const float4* p4 = (const float4*)g_part;
            const int stride4 = N_ROWS * OUT_DIM / 4;    // 32768

            float4 m = p4[(size_t)(half * 9) * stride4 + idx];
            #pragma unroll
            for (int j = 1; j < 9; j++) {
                float4 v = p4[(size_t)(half * 9 + j) * stride4 + idx];
                m.x = fmaxf(m.x, v.x);
                m.y = fmaxf(m.y, v.y);
                m.z = fmaxf(m.z, v.z);
                m.w = fmaxf(m.w, v.w);
            }

            m.x = fmaxf(m.x, __shfl_xor_sync(0xffffffffu, m.x, 1));
            m.y = fmaxf(m.y, __shfl_xor_sync(0xffffffffu, m.y, 1));
            m.z = fmaxf(m.z, __shfl_xor_sync(0xffffffffu, m.z, 1));
            m.w = fmaxf(m.w, __shfl_xor_sync(0xffffffffu, m.w, 1));

            if (half == 0) {
                float4 b = __ldg(&((const float4*)bias)[idx & (OUT_DIM / 4 - 1)]);
                m.x += b.x; m.y += b.y; m.z += b.z; m.w += b.w;
                ((float4*)out)[idx] = m;
            }
        }
    }

    // ---- counter reset (deterministic across graph replays) ----
    __syncthreads();
    if (t == 0) {
        unsigned d = atomicAdd(&g_depart, 1u);
        if (d == NCTAS - 1) {            // last CTA: everyone passed the barrier
            g_arrive = 0;
            __threadfence();
            g_depart = 0;
        }
    }
}

extern "C" void kernel_launch(void* const* d_in, const int* in_sizes, int n_in,
                              void* d_out, int out_size)
{
    const float* x    = (const float*)d_in[0];   // [128, 1024]
    const float* w    = (const float*)d_in[1];   // [1024, 1024]
    const float* bias = (const float*)d_in[2];   // [1024]
    float* out = (float*)d_out;                  // [128, 1024]

    cudaFuncSetAttribute(tropical_fused,
                         cudaFuncAttributeMaxDynamicSharedMemorySize, SMEM_BYTES);

    dim3 grid(8, KSPLIT);                        // 144 CTAs, one wave
    tropical_fused<<<grid, THREADS, SMEM_BYTES>>>(x, w, bias, out);
}

// round 5
// speedup vs baseline: 1.3582x; 1.3582x over previous
#include <cuda_runtime.h>
#include <float.h>

// TropicalLinear: out[n,o] = bias[o] + max_k( x[n,k] + w[o,k] )
// N=128, IN=1024, OUT=1024, fp32.  (soft - stop_grad(soft) == 0 exactly)
//
// Candidate-pruned algorithm (exact for ANY input):
//   winner k for (n,o) must satisfy x[n,k] >= max_k x[n,k] - (wmax - wmin).
//   K1: transpose w -> wT[k][o] (+ per-block w min/max partials)
//   K2: per row n: block max of x row, global w spread, compact candidates,
//       gather-max over coalesced wT rows, + bias.

#define N_ROWS  128
#define IN_DIM  1024
#define OUT_DIM 1024
#define MAXC    IN_DIM          // full-safety candidate capacity

__device__ float g_wT[IN_DIM * OUT_DIM];     // wT[k][o] = w[o][k]  (4 MB)
__device__ float2 g_wrng[128];               // per-K1-block (min, max)

// ---------------------------------------------------------------- K1
__global__ __launch_bounds__(256)
void k1_transpose_range(const float* __restrict__ w)
{
    __shared__ float tile[32][33];
    const int b    = blockIdx.x;        // 0..127
    const int t    = threadIdx.x;
    const int lane = t & 31;
    const int wp   = t >> 5;            // 0..7

    float wmn =  FLT_MAX;
    float wmx = -FLT_MAX;

    #pragma unroll 1
    for (int it = 0; it < 8; it++) {
        const int tile_id = b * 8 + it;          // 0..1023
        const int tr = tile_id >> 5;             // k-tile  (0..31)
        const int tc = tile_id & 31;             // o-tile  (0..31)

        // load w[o = tc*32 + r][k = tr*32 + lane], coalesced 128B rows
        #pragma unroll
        for (int r = wp; r < 32; r += 8) {
            float v = __ldg(&w[(size_t)(tc * 32 + r) * IN_DIM + tr * 32 + lane]);
            wmn = fminf(wmn, v);
            wmx = fmaxf(wmx, v);
            tile[r][lane] = v;
        }
        __syncthreads();
        // store wT[k = tr*32 + r][o = tc*32 + lane], coalesced
        #pragma unroll
        for (int r = wp; r < 32; r += 8) {
            g_wT[(size_t)(tr * 32 + r) * OUT_DIM + tc * 32 + lane] = tile[lane][r];
        }
        __syncthreads();
    }

    // block-reduce (min, max)
    #pragma unroll
    for (int d = 16; d; d >>= 1) {
        wmn = fminf(wmn, __shfl_xor_sync(0xffffffffu, wmn, d));
        wmx = fmaxf(wmx, __shfl_xor_sync(0xffffffffu, wmx, d));
    }
    __shared__ float s_mn[8], s_mx[8];
    if (lane == 0) { s_mn[wp] = wmn; s_mx[wp] = wmx; }
    __syncthreads();
    if (t == 0) {
        float mn = s_mn[0], mx = s_mx[0];
        #pragma unroll
        for (int i = 1; i < 8; i++) {
            mn = fminf(mn, s_mn[i]);
            mx = fmaxf(mx, s_mx[i]);
        }
        g_wrng[b] = make_float2(mn, mx);
    }
}

// ---------------------------------------------------------------- K2
__global__ __launch_bounds__(256)
void k2_prune_gather(const float* __restrict__ x,
                     const float* __restrict__ bias,
                     float* __restrict__ out)
{
    const int n    = blockIdx.x;        // 0..127
    const int t    = threadIdx.x;
    const int lane = t & 31;
    const int wp   = t >> 5;

    __shared__ float s_xm[8];
    __shared__ float s_mn[4], s_mx[4];
    __shared__ float s_thr;
    __shared__ int   s_cnt;
    __shared__ float s_cx[MAXC];
    __shared__ int   s_ck[MAXC];

    // ---- load this row's x (float4 per thread) + row max ----
    const float4 xv = __ldg(&((const float4*)x)[(size_t)n * (IN_DIM / 4) + t]);
    float xm = fmaxf(fmaxf(xv.x, xv.y), fmaxf(xv.z, xv.w));
    #pragma unroll
    for (int d = 16; d; d >>= 1)
        xm = fmaxf(xm, __shfl_xor_sync(0xffffffffu, xm, d));
    if (lane == 0) s_xm[wp] = xm;

    // ---- reduce global w spread from K1 partials (threads 0..127) ----
    float wmn = FLT_MAX, wmx = -FLT_MAX;
    if (t < 128) {
        float2 r = g_wrng[t];
        wmn = r.x; wmx = r.y;
    }
    #pragma unroll
    for (int d = 16; d; d >>= 1) {
        wmn = fminf(wmn, __shfl_xor_sync(0xffffffffu, wmn, d));
        wmx = fmaxf(wmx, __shfl_xor_sync(0xffffffffu, wmx, d));
    }
    if (lane == 0 && wp < 4) { s_mn[wp] = wmn; s_mx[wp] = wmx; }
    __syncthreads();

    if (t == 0) {
        float m = s_xm[0];
        #pragma unroll
        for (int i = 1; i < 8; i++) m = fmaxf(m, s_xm[i]);
        float mn = s_mn[0], mx = s_mx[0];
        #pragma unroll
        for (int i = 1; i < 4; i++) {
            mn = fminf(mn, s_mn[i]);
            mx = fmaxf(mx, s_mx[i]);
        }
        // slack 1e-5 >> any fp32 sum-rounding reorder at |val| ~ 5
        s_thr = m - (mx - mn) - 1e-5f;
        s_cnt = 0;
    }
    __syncthreads();

    // ---- compact candidates (k, x[n,k]) with x >= thr ----
    {
        const float thr = s_thr;
        const int   k0  = t * 4;
        float v[4] = {xv.x, xv.y, xv.z, xv.w};
        #pragma unroll
        for (int j = 0; j < 4; j++) {
            if (v[j] >= thr) {
                int p = atomicAdd(&s_cnt, 1);
                s_ck[p] = k0 + j;
                s_cx[p] = v[j];
            }
        }
    }
    __syncthreads();
    const int cnt = s_cnt;

    // ---- gather-max over candidate rows of wT (coalesced along o) ----
    const float4* wt4 = (const float4*)g_wT;   // [IN_DIM][OUT_DIM/4]
    float4 acc = make_float4(-FLT_MAX, -FLT_MAX, -FLT_MAX, -FLT_MAX);

    int c = 0;
    for (; c + 4 <= cnt; c += 4) {
        const int k0 = s_ck[c],     k1 = s_ck[c + 1];
        const int k2 = s_ck[c + 2], k3 = s_ck[c + 3];
        const float x0 = s_cx[c],     x1 = s_cx[c + 1];
        const float x2 = s_cx[c + 2], x3 = s_cx[c + 3];
        float4 w0 = wt4[(size_t)k0 * (OUT_DIM / 4) + t];
        float4 w1 = wt4[(size_t)k1 * (OUT_DIM / 4) + t];
        float4 w2 = wt4[(size_t)k2 * (OUT_DIM / 4) + t];
        float4 w3 = wt4[(size_t)k3 * (OUT_DIM / 4) + t];
        acc.x = fmaxf(acc.x, x0 + w0.x); acc.y = fmaxf(acc.y, x0 + w0.y);
        acc.z = fmaxf(acc.z, x0 + w0.z); acc.w = fmaxf(acc.w, x0 + w0.w);
        acc.x = fmaxf(acc.x, x1 + w1.x); acc.y = fmaxf(acc.y, x1 + w1.y);
        acc.z = fmaxf(acc.z, x1 + w1.z); acc.w = fmaxf(acc.w, x1 + w1.w);
        acc.x = fmaxf(acc.x, x2 + w2.x); acc.y = fmaxf(acc.y, x2 + w2.y);
        acc.z = fmaxf(acc.z, x2 + w2.z); acc.w = fmaxf(acc.w, x2 + w2.w);
        acc.x = fmaxf(acc.x, x3 + w3.x); acc.y = fmaxf(acc.y, x3 + w3.y);
        acc.z = fmaxf(acc.z, x3 + w3.z); acc.w = fmaxf(acc.w, x3 + w3.w);
    }
    for (; c < cnt; c++) {
        const int   k = s_ck[c];
        const float xc = s_cx[c];
        float4 wv = wt4[(size_t)k * (OUT_DIM / 4) + t];
        acc.x = fmaxf(acc.x, xc + wv.x);
        acc.y = fmaxf(acc.y, xc + wv.y);
        acc.z = fmaxf(acc.z, xc + wv.z);
        acc.w = fmaxf(acc.w, xc + wv.w);
    }

    // ---- + bias, store ----
    float4 bv = __ldg(&((const float4*)bias)[t]);
    acc.x += bv.x; acc.y += bv.y; acc.z += bv.z; acc.w += bv.w;
    ((float4*)out)[(size_t)n * (OUT_DIM / 4) + t] = acc;
}

extern "C" void kernel_launch(void* const* d_in, const int* in_sizes, int n_in,
                              void* d_out, int out_size)
{
    const float* x    = (const float*)d_in[0];   // [128, 1024]
    const float* w    = (const float*)d_in[1];   // [1024, 1024]
    const float* bias = (const float*)d_in[2];   // [1024]
    float* out = (float*)d_out;                  // [128, 1024]

    k1_transpose_range<<<128, 256>>>(w);
    k2_prune_gather<<<N_ROWS, 256>>>(x, bias, out);
}

// round 6
// speedup vs baseline: 1.7627x; 1.2978x over previous
#include <cuda_runtime.h>
#include <float.h>

// TropicalLinear: out[n,o] = bias[o] + max_k( x[n,k] + w[o,k] )
// N=128, IN=1024, OUT=1024, fp32.  (soft - stop_grad(soft) == 0 exactly)
//
// Exact candidate pruning: winner k for (n,o) must satisfy
//   x[n,k] >= max_k x[n,k] - (wmax - wmin) - slack.
// Fused single kernel, 256 CTAs co-resident (launch_bounds(256,2)):
//   stage A: transpose w -> wT[k][o] + per-CTA w min/max partials
//   grid barrier
//   stage B: per (row, o-half): row max, global w spread, compact candidates,
//            batched-MLP gather-max over wT rows (L2-hot), + bias.

#define N_ROWS  128
#define IN_DIM  1024
#define OUT_DIM 1024
#define NCTAS   256
#define THREADS 256

__device__ float  g_wT[IN_DIM * OUT_DIM];   // wT[k][o] = w[o][k]  (4 MB)
__device__ float2 g_wrng[NCTAS];            // per-CTA (min, max) of w
__device__ unsigned g_arrive;               // zero-init; reset each run
__device__ unsigned g_depart;               // zero-init; reset each run

__global__ __launch_bounds__(THREADS, 2)
void tropical_fused(const float* __restrict__ x, const float* __restrict__ w,
                    const float* __restrict__ bias, float* __restrict__ out)
{
    __shared__ float tile[32][33];          // stage A transpose staging
    __shared__ int   s_ck[IN_DIM + 8];      // candidate k (padded)
    __shared__ float s_cx[IN_DIM + 8];      // candidate x value
    __shared__ float s_xm[8], s_mn[8], s_mx[8];
    __shared__ float s_thr;
    __shared__ int   s_cnt;

    const int b    = blockIdx.x;            // 0..255
    const int t    = threadIdx.x;
    const int lane = t & 31;
    const int wp   = t >> 5;                // 0..7

    // ================= stage A: transpose + w range =================
    float wmn =  FLT_MAX;
    float wmx = -FLT_MAX;
    #pragma unroll 1
    for (int it = 0; it < 4; it++) {
        const int tile_id = b * 4 + it;     // 0..1023
        const int tr = tile_id >> 5;        // k-tile
        const int tc = tile_id & 31;        // o-tile
        #pragma unroll
        for (int r = wp; r < 32; r += 8) {
            float v = __ldg(&w[(size_t)(tc * 32 + r) * IN_DIM + tr * 32 + lane]);
            wmn = fminf(wmn, v);
            wmx = fmaxf(wmx, v);
            tile[r][lane] = v;
        }
        __syncthreads();
        #pragma unroll
        for (int r = wp; r < 32; r += 8)
            g_wT[(size_t)(tr * 32 + r) * OUT_DIM + tc * 32 + lane] = tile[lane][r];
        __syncthreads();
    }
    #pragma unroll
    for (int d = 16; d; d >>= 1) {
        wmn = fminf(wmn, __shfl_xor_sync(0xffffffffu, wmn, d));
        wmx = fmaxf(wmx, __shfl_xor_sync(0xffffffffu, wmx, d));
    }
    if (lane == 0) { s_mn[wp] = wmn; s_mx[wp] = wmx; }
    __syncthreads();
    if (t == 0) {
        float mn = s_mn[0], mx = s_mx[0];
        #pragma unroll
        for (int i = 1; i < 8; i++) {
            mn = fminf(mn, s_mn[i]);
            mx = fmaxf(mx, s_mx[i]);
        }
        g_wrng[b] = make_float2(mn, mx);
    }

    // ================= grid barrier (R4-validated pattern) ==========
    __syncthreads();
    __threadfence();
    if (t == 0) {
        atomicAdd(&g_arrive, 1u);
        while (*(volatile unsigned*)&g_arrive < NCTAS) { }
    }
    __syncthreads();
    __threadfence();

    // ================= stage B: prune + gather ======================
    const int n    = b >> 1;                // row 0..127
    const int half = b & 1;                 // o-half (512 outputs)

    // x row load (256 float4 = full row) + row max — overlaps wrng load
    const float4 xv = __ldg(&((const float4*)x)[(size_t)n * (IN_DIM / 4) + t]);
    float xm = fmaxf(fmaxf(xv.x, xv.y), fmaxf(xv.z, xv.w));

    float2 rr = g_wrng[t];                  // 256 partials, one per thread
    float rmn = rr.x, rmx = rr.y;

    #pragma unroll
    for (int d = 16; d; d >>= 1) {
        xm  = fmaxf(xm,  __shfl_xor_sync(0xffffffffu, xm,  d));
        rmn = fminf(rmn, __shfl_xor_sync(0xffffffffu, rmn, d));
        rmx = fmaxf(rmx, __shfl_xor_sync(0xffffffffu, rmx, d));
    }
    if (lane == 0) { s_xm[wp] = xm; s_mn[wp] = rmn; s_mx[wp] = rmx; }
    __syncthreads();

    if (t == 0) {
        float m  = s_xm[0];
        float mn = s_mn[0], mx = s_mx[0];
        #pragma unroll
        for (int i = 1; i < 8; i++) {
            m  = fmaxf(m,  s_xm[i]);
            mn = fminf(mn, s_mn[i]);
            mx = fmaxf(mx, s_mx[i]);
        }
        float slack = 1e-5f + 1e-6f * (fabsf(m) + fmaxf(fabsf(mx), fabsf(mn)));
        s_thr = m - (mx - mn) - slack;
        s_cnt = 0;
    }
    __syncthreads();

    // compact candidates
    {
        const float thr = s_thr;
        float v[4] = {xv.x, xv.y, xv.z, xv.w};
        #pragma unroll
        for (int j = 0; j < 4; j++) {
            if (v[j] >= thr) {
                int p = atomicAdd(&s_cnt, 1);
                s_ck[p] = t * 4 + j;
                s_cx[p] = v[j];
            }
        }
    }
    __syncthreads();
    const int cnt  = s_cnt;                  // >= 1 always (row max qualifies)
    const int cntp = (cnt + 7) & ~7;
    if (t < cntp - cnt) {                    // pad with candidate 0 (idempotent)
        s_ck[cnt + t] = s_ck[0];
        s_cx[cnt + t] = s_cx[0];
    }
    __syncthreads();

    // gather: 2 threads per float4 output, parity-split candidates,
    // 4 independent LDG.128 per batch of 8 candidates.
    const int f4  = t >> 1;                  // 0..127
    const int par = t & 1;
    const int col = half * 128 + f4;         // global float4 column

    const float4* wt4 = (const float4*)g_wT; // [IN_DIM][OUT_DIM/4]
    float4 acc = make_float4(-FLT_MAX, -FLT_MAX, -FLT_MAX, -FLT_MAX);

    for (int c0 = par; c0 < cntp; c0 += 8) {
        const int   k0 = s_ck[c0],     k1 = s_ck[c0 + 2];
        const int   k2 = s_ck[c0 + 4], k3 = s_ck[c0 + 6];
        const float x0 = s_cx[c0],     x1 = s_cx[c0 + 2];
        const float x2 = s_cx[c0 + 4], x3 = s_cx[c0 + 6];
        float4 w0 = wt4[(size_t)k0 * (OUT_DIM / 4) + col];
        float4 w1 = wt4[(size_t)k1 * (OUT_DIM / 4) + col];
        float4 w2 = wt4[(size_t)k2 * (OUT_DIM / 4) + col];
        float4 w3 = wt4[(size_t)k3 * (OUT_DIM / 4) + col];
        acc.x = fmaxf(acc.x, x0 + w0.x); acc.y = fmaxf(acc.y, x0 + w0.y);
        acc.z = fmaxf(acc.z, x0 + w0.z); acc.w = fmaxf(acc.w, x0 + w0.w);
        acc.x = fmaxf(acc.x, x1 + w1.x); acc.y = fmaxf(acc.y, x1 + w1.y);
        acc.z = fmaxf(acc.z, x1 + w1.z); acc.w = fmaxf(acc.w, x1 + w1.w);
        acc.x = fmaxf(acc.x, x2 + w2.x); acc.y = fmaxf(acc.y, x2 + w2.y);
        acc.z = fmaxf(acc.z, x2 + w2.z); acc.w = fmaxf(acc.w, x2 + w2.w);
        acc.x = fmaxf(acc.x, x3 + w3.x); acc.y = fmaxf(acc.y, x3 + w3.y);
        acc.z = fmaxf(acc.z, x3 + w3.z); acc.w = fmaxf(acc.w, x3 + w3.w);
    }

    // combine the two parity partials
    acc.x = fmaxf(acc.x, __shfl_xor_sync(0xffffffffu, acc.x, 1));
    acc.y = fmaxf(acc.y, __shfl_xor_sync(0xffffffffu, acc.y, 1));
    acc.z = fmaxf(acc.z, __shfl_xor_sync(0xffffffffu, acc.z, 1));
    acc.w = fmaxf(acc.w, __shfl_xor_sync(0xffffffffu, acc.w, 1));

    if (par == 0) {
        float4 bv = __ldg(&((const float4*)bias)[col]);
        acc.x += bv.x; acc.y += bv.y; acc.z += bv.z; acc.w += bv.w;
        ((float4*)out)[(size_t)n * (OUT_DIM / 4) + col] = acc;
    }

    // ---- counter reset (safe: last departing CTA resets both) ----
    __syncthreads();
    if (t == 0) {
        unsigned d = atomicAdd(&g_depart, 1u);
        if (d == NCTAS - 1) {
            g_arrive = 0;
            __threadfence();
            g_depart = 0;
        }
    }
}

extern "C" void kernel_launch(void* const* d_in, const int* in_sizes, int n_in,
                              void* d_out, int out_size)
{
    const float* x    = (const float*)d_in[0];   // [128, 1024]
    const float* w    = (const float*)d_in[1];   // [1024, 1024]
    const float* bias = (const float*)d_in[2];   // [1024]
    float* out = (float*)d_out;                  // [128, 1024]

    tropical_fused<<<NCTAS, THREADS>>>(x, w, bias, out);
}